// round 17
// baseline (speedup 1.0000x reference)
#include <cuda_runtime.h>
#include <cuda_bf16.h>
#include <cstdint>

// BatchRankingLoss: G=511 groups of d=256 decoys.
// loss = sum_{g,i,j} w_ij * max(0, 1 + y_ij*(o_i - o_j)) / (G*d*(d-1))
//   y_ij = -1 if (t_i - t_j) < 0 else +1 ;  w_ij = |t_i - t_j| > 0.1
//
// R16 diagnosis: the 4-row-blocked layout put lane u's LDS.64 at byte 32u+8s
// -> bank (8u+2s) mod 32 -> 8-WAY BANK CONFLICT on every inner LDS; the smem
// crossbar (128/N B/cyc) was the saturated pipe all along (explains the
// 9.7-10.3us plateau across all instruction-diet changes).
//
// This version: 32x32 TILES with WARP-UNIFORM column loads.
//   - warp lanes = 32 rows of tile I (row (o,t) in regs, loaded once/tile)
//   - columns j of tile J iterated uniformly: all lanes read ot[J*32+j]
//     -> HW broadcast, N=1, conflict-free, 1 LDS warp-instr per 32 terms.
//   - symmetry at tile granularity: 36 tiles (8 diagonal w=1, 28 upper w=2);
//     diagonal handles i==j automatically (dt=0 -> gated out). total = sum of
//     weighted tile sums over ordered in-tile pairs; NO edge cases at all.
//   - CTA = 288 threads = 9 warps = ONE group; 36/9 = 4 tiles per warp.
//     Per-tile sum folded with its weight via one FFMA.
//
// Fused reduction: group sums -> scratch; last CTA (ticket) writes d_out and
// resets the ticket -> graph-replay deterministic.

#define D      256
#define THRESH 0.1f

__device__ float    g_group_sums[4096];
__device__ unsigned g_ticket;   // zero-init; reset by last CTA each call

// 36 upper-triangle tile pairs (I <= J), 4 consecutive per warp.
__constant__ unsigned char TI[36] = {
    0,0,0,0, 0,0,0,0, 1,1,1,1, 1,1,1,2, 2,2,2,2,
    2,3,3,3, 3,3,4,4, 4,4,5,5, 5,6,6,7};
__constant__ unsigned char TJ[36] = {
    0,1,2,3, 4,5,6,7, 1,2,3,4, 5,6,7,2, 3,4,5,6,
    7,3,4,5, 6,7,4,5, 6,7,5,6, 7,6,7,7};

// v = (o_j, t_j). 7 SASS ops, guard if-converted to @p FADD.
__device__ __forceinline__ void acc_term(float& acc, float oi, float ti,
                                         float2 v)
{
    const float dt = ti - v.y;
    const float dd = oi - v.x;
    // y*do via sign-bit xor (y=-1 iff dt<0; dt==+-0 is weighted out)
    const uint32_t s =
        __float_as_uint(dd) ^ (__float_as_uint(dt) & 0x80000000u);
    const float q = fmaxf(0.0f, 1.0f + __uint_as_float(s));
    if (fabsf(dt) > THRESH) acc += q;
}

__global__ __launch_bounds__(288) void ranking_loss_kernel(
    const float* __restrict__ o_in,   // [B,1] -> [B]
    const float* __restrict__ t_in,   // [B]
    float* __restrict__ out,
    int G)
{
    __shared__ __align__(16) float2 ot[D];   // (o, t) per row
    __shared__ float wsum[9];
    __shared__ bool  is_last;

    const int tid  = threadIdx.x;
    const int w    = tid >> 5;         // warp 0..8
    const int lane = tid & 31;
    const int g    = blockIdx.x;

    if (tid < D)                        // coalesced row load -> smem
        ot[tid] = make_float2(o_in[g * D + tid], t_in[g * D + tid]);
    __syncthreads();

    float acc = 0.f;
#pragma unroll
    for (int e = 0; e < 4; ++e) {
        const int tix = 4 * w + e;
        const int I = TI[tix];          // LDC, warp-uniform
        const int J = TJ[tix];
        const float2 rv = ot[I * 32 + lane];   // per-lane row (2-way, 1/tile)
        const float  oi = rv.x, ti = rv.y;
        const float2* cb = ot + J * 32;        // warp-uniform column base

        float tacc = 0.f;
#pragma unroll 8
        for (int j = 0; j < 32; ++j) {
            const float2 v = cb[j];     // uniform address -> LDS broadcast
            acc_term(tacc, oi, ti, v);
        }
        // diagonal tile weight 1, off-diagonal weight 2 (covers (J,I))
        acc = fmaf((I == J) ? 1.0f : 2.0f, tacc, acc);
    }

    // CTA reduce (9 warps)
#pragma unroll
    for (int off = 16; off > 0; off >>= 1)
        acc += __shfl_xor_sync(0xffffffffu, acc, off);
    if (lane == 0) wsum[w] = acc;
    __syncthreads();

    if (tid == 0) {
        float s = 0.f;
#pragma unroll
        for (int i = 0; i < 9; ++i) s += wsum[i];
        g_group_sums[g] = s;
        __threadfence();
        unsigned old = atomicAdd(&g_ticket, 1u);
        is_last = (old == (unsigned)(G - 1));
    }
    __syncthreads();

    if (is_last && tid < 256) {
        __threadfence();                    // acquire other CTAs' sums
        float v = (tid < G) ? g_group_sums[tid] : 0.f;
        if (tid + 256 < G) v += g_group_sums[tid + 256];

#pragma unroll
        for (int off = 16; off > 0; off >>= 1)
            v += __shfl_xor_sync(0xffffffffu, v, off);
        if (lane == 0) wsum[w] = v;
        __syncwarp();
        if (tid == 0) {
            // wait for the 8 participating warps' stores
            __threadfence_block();
        }
    }
    if (is_last) {
        __syncthreads();                    // all 288 threads arrive
        if (tid == 0) {
            float s = 0.f;
#pragma unroll
            for (int i = 0; i < 8; ++i) s += wsum[i];
            const float inv_n = 1.0f / ((float)G * (float)D * (float)(D - 1));
            out[0] = s * inv_n;             // tile weights already applied
            g_ticket = 0;                   // reset for next graph replay
        }
    }
}

extern "C" void kernel_launch(void* const* d_in, const int* in_sizes, int n_in,
                              void* d_out, int out_size)
{
    const float* o = (const float*)d_in[0];  // input  [B,1] f32
    const float* t = (const float*)d_in[1];  // gdt_ts [B]   f32
    float* out = (float*)d_out;

    const int B = in_sizes[1];
    const int K = B / D;            // 512
    const int G = K - 1;            // 511 (reference skips final group)

    ranking_loss_kernel<<<G, 288>>>(o, t, out, G);
}